// round 7
// baseline (speedup 1.0000x reference)
#include <cuda_runtime.h>
#include <cuda_bf16.h>
#include <cstdint>

// ---------------------------------------------------------------------------
// DeltaOnlyModel: B=256, L=2048, H=V=64.
// Encoder collapses to 64-entry vocab tables (k normalized, v, q, thr^2).
// Scan: 1 block = 1 WARP per batch element; thread i owns M rows i and i+32
// entirely in registers. The gate reduction is a pure intra-warp shfl
// butterfly -- no shared-memory exchange, no __syncthreads in the loop.
// ---------------------------------------------------------------------------

#define H 64
#define V 64
#define L 2048
#define B 256

__device__ float g_ktab[V * H];
__device__ float g_vtab[V * H];
__device__ float g_qtab[V * H];
__device__ float g_thr2[V];

typedef unsigned long long ull;

__device__ __forceinline__ ull ffma2(ull a, ull b, ull c) {
    ull d;
    asm("fma.rn.f32x2 %0, %1, %2, %3;" : "=l"(d) : "l"(a), "l"(b), "l"(c));
    return d;
}
__device__ __forceinline__ ull fadd2(ull a, ull b) {
    ull d;
    asm("add.rn.f32x2 %0, %1, %2;" : "=l"(d) : "l"(a), "l"(b));
    return d;
}
__device__ __forceinline__ ull pack2(float lo, float hi) {
    ull d;
    asm("mov.b64 %0, {%1, %2};" : "=l"(d) : "f"(lo), "f"(hi));
    return d;
}
__device__ __forceinline__ void unpack2(ull a, float& lo, float& hi) {
    asm("mov.b64 {%0, %1}, %2;" : "=f"(lo), "=f"(hi) : "l"(a));
}
__device__ __forceinline__ float hsum4(ull a0, ull a1, ull a2, ull a3) {
    float lo, hi;
    unpack2(fadd2(fadd2(a0, a1), fadd2(a2, a3)), lo, hi);
    return lo + hi;
}

// ---------------------------------------------------------------------------
// Table builder: one block per vocab entry, 64 threads.
// ---------------------------------------------------------------------------
__global__ void build_tables(const float* __restrict__ embed,
                             const float* __restrict__ w1,
                             const float* __restrict__ b1,
                             const float* __restrict__ w2,
                             const float* __restrict__ b2,
                             const float* __restrict__ ln_g,
                             const float* __restrict__ ln_b,
                             const float* __restrict__ wk,
                             const float* __restrict__ wv,
                             const float* __restrict__ wq) {
    __shared__ float se[H];
    __shared__ float su[2 * H];
    __shared__ float sh[H];
    __shared__ float sred[H];

    const int c = blockIdx.x;
    const int j = threadIdx.x;

    se[j] = embed[c * H + j];
    __syncthreads();

    #pragma unroll
    for (int rep = 0; rep < 2; rep++) {
        const int m = j + rep * H;
        float a = b1[m];
        #pragma unroll 8
        for (int i = 0; i < H; i++) a = fmaf(se[i], w1[i * (2 * H) + m], a);
        su[m] = fmaxf(a, 0.0f);
    }
    __syncthreads();

    float f = b2[j];
    #pragma unroll 8
    for (int m = 0; m < 2 * H; m++) f = fmaf(su[m], w2[m * H + j], f);

    const float s = se[j] + f;
    sh[j] = s;
    __syncthreads();

    float mu = 0.0f;
    #pragma unroll 8
    for (int i = 0; i < H; i++) mu += sh[i];
    mu *= (1.0f / H);
    float var = 0.0f;
    #pragma unroll 8
    for (int i = 0; i < H; i++) { float d = sh[i] - mu; var = fmaf(d, d, var); }
    var *= (1.0f / H);
    const float hn = (s - mu) * rsqrtf(var + 1e-5f) * ln_g[j] + ln_b[j];
    __syncthreads();
    sh[j] = hn;
    __syncthreads();

    float kr = 0.0f;
    #pragma unroll 8
    for (int i = 0; i < H; i++) kr = fmaf(sh[i], wk[i * H + j], kr);
    sred[j] = kr * kr;
    __syncthreads();
    float nk = 0.0f;
    #pragma unroll 8
    for (int i = 0; i < H; i++) nk += sred[i];
    nk = fmaxf(sqrtf(nk), 1e-12f);
    g_ktab[c * H + j] = kr / nk;
    __syncthreads();

    float vr = 0.0f;
    #pragma unroll 8
    for (int i = 0; i < H; i++) vr = fmaf(sh[i], wv[i * H + j], vr);
    g_vtab[c * H + j] = vr;
    sred[j] = vr * vr;
    __syncthreads();
    float nv = 0.0f;
    #pragma unroll 8
    for (int i = 0; i < H; i++) nv += sred[i];
    if (j == 0) g_thr2[c] = 0.16f * nv;

    float qr = 0.0f;
    #pragma unroll 8
    for (int i = 0; i < H; i++) qr = fmaf(sh[i], wq[i * H + j], qr);
    g_qtab[c * H + j] = qr;
}

// ---------------------------------------------------------------------------
// Scan kernel: 32 threads/block, 2 M-rows per thread.
// ---------------------------------------------------------------------------
__global__ __launch_bounds__(32) void scan_kernel(const int* __restrict__ x,
                                                  const float* __restrict__ wo,
                                                  const float* __restrict__ bo,
                                                  float* __restrict__ out) {
    __shared__ __align__(16) float sk[V * H];    // 16 KB normalized k
    __shared__ __align__(8)  float sv2[V * H];   // 16 KB v, packed (row i, row i+32)
    __shared__ float sthr[V];
    __shared__ int   sx[L];                      // 8 KB tokens
    __shared__ float sfin[H];

    const int b   = blockIdx.x;
    const int tid = threadIdx.x;                 // 0..31

    // Load tables. v is repacked so lane i reads rows (i, i+32) with one LDS.64.
    for (int i = tid; i < V * H; i += 32) sk[i] = g_ktab[i];
    for (int c = 0; c < V; c += 1) {
        // each lane packs its own pair for vocab entry c+? -- strided by lanes:
        // do two vocab entries per outer step to keep all lanes busy
    }
    for (int i = tid; i < V * 32; i += 32) {
        const int c = i >> 5;
        const int ln = i & 31;
        sv2[(c << 6) + 2 * ln]     = g_vtab[(c << 6) + ln];
        sv2[(c << 6) + 2 * ln + 1] = g_vtab[(c << 6) + ln + 32];
    }
    for (int i = tid; i < V; i += 32) sthr[i] = g_thr2[i];
    const int* xb = x + b * L;
    for (int i = tid; i < L; i += 32) sx[i] = xb[i];
    __syncthreads();

    // M rows tid and tid+32, packed f32x2: 32 ull each.
    ull mA[32], mB[32];
    #pragma unroll
    for (int i = 0; i < 32; i++) { mA[i] = 0ULL; mB[i] = 0ULL; }

    for (int t = 0; t < L; t++) {
        const int tok = sx[t];
        const ulonglong2* kp = reinterpret_cast<const ulonglong2*>(sk + (tok << 6));

        // preds for both owned rows (8 independent accumulators)
        ull a0 = 0, a1 = 0, a2 = 0, a3 = 0;
        ull b0 = 0, b1 = 0, b2 = 0, b3 = 0;
        #pragma unroll
        for (int j = 0; j < 8; j++) {
            const ulonglong2 kA = kp[2 * j];
            const ulonglong2 kB = kp[2 * j + 1];
            a0 = ffma2(mA[4 * j + 0], kA.x, a0);
            a1 = ffma2(mA[4 * j + 1], kA.y, a1);
            a2 = ffma2(mA[4 * j + 2], kB.x, a2);
            a3 = ffma2(mA[4 * j + 3], kB.y, a3);
            b0 = ffma2(mB[4 * j + 0], kA.x, b0);
            b1 = ffma2(mB[4 * j + 1], kA.y, b1);
            b2 = ffma2(mB[4 * j + 2], kB.x, b2);
            b3 = ffma2(mB[4 * j + 3], kB.y, b3);
        }
        const float P0 = hsum4(a0, a1, a2, a3);
        const float P1 = hsum4(b0, b1, b2, b3);

        const float2 vp = reinterpret_cast<const float2*>(sv2 + (tok << 6))[tid];
        const float d0 = vp.x - P0;
        const float d1 = vp.y - P1;

        // ||delta||^2: intra-warp butterfly only
        float s = fmaf(d0, d0, d1 * d1);
        #pragma unroll
        for (int o = 16; o > 0; o >>= 1)
            s += __shfl_xor_sync(0xffffffffu, s, o);

        if (s > sthr[tok]) {
            const ull dd0 = pack2(d0, d0);
            const ull dd1 = pack2(d1, d1);
            #pragma unroll
            for (int j = 0; j < 8; j++) {
                const ulonglong2 kA = kp[2 * j];
                const ulonglong2 kB = kp[2 * j + 1];
                mA[4 * j + 0] = ffma2(dd0, kA.x, mA[4 * j + 0]);
                mA[4 * j + 1] = ffma2(dd0, kA.y, mA[4 * j + 1]);
                mA[4 * j + 2] = ffma2(dd0, kB.x, mA[4 * j + 2]);
                mA[4 * j + 3] = ffma2(dd0, kB.y, mA[4 * j + 3]);
                mB[4 * j + 0] = ffma2(dd1, kA.x, mB[4 * j + 0]);
                mB[4 * j + 1] = ffma2(dd1, kA.y, mB[4 * j + 1]);
                mB[4 * j + 2] = ffma2(dd1, kB.x, mB[4 * j + 2]);
                mB[4 * j + 3] = ffma2(dd1, kB.y, mB[4 * j + 3]);
            }
        }
    }

    // Readout: q = q_tab[last token]; read = relu(M q); out = read @ wo + bo
    const int tokL = sx[L - 1];
    const ulonglong2* qp = reinterpret_cast<const ulonglong2*>(g_qtab + (tokL << 6));
    ull a0 = 0, a1 = 0, a2 = 0, a3 = 0;
    ull b0 = 0, b1 = 0, b2 = 0, b3 = 0;
    #pragma unroll
    for (int j = 0; j < 8; j++) {
        const ulonglong2 qA = qp[2 * j];
        const ulonglong2 qB = qp[2 * j + 1];
        a0 = ffma2(mA[4 * j + 0], qA.x, a0);
        a1 = ffma2(mA[4 * j + 1], qA.y, a1);
        a2 = ffma2(mA[4 * j + 2], qB.x, a2);
        a3 = ffma2(mA[4 * j + 3], qB.y, a3);
        b0 = ffma2(mB[4 * j + 0], qA.x, b0);
        b1 = ffma2(mB[4 * j + 1], qA.y, b1);
        b2 = ffma2(mB[4 * j + 2], qB.x, b2);
        b3 = ffma2(mB[4 * j + 3], qB.y, b3);
    }
    sfin[tid]      = fmaxf(hsum4(a0, a1, a2, a3), 0.0f);
    sfin[tid + 32] = fmaxf(hsum4(b0, b1, b2, b3), 0.0f);
    __syncthreads();

    #pragma unroll
    for (int rep = 0; rep < 2; rep++) {
        const int c = tid + rep * 32;
        float oacc = bo[c];
        #pragma unroll 8
        for (int i = 0; i < H; i++) oacc = fmaf(sfin[i], wo[(i << 6) + c], oacc);
        out[(b << 6) + c] = oacc;
    }
}

// ---------------------------------------------------------------------------
// Inputs: x, embed, w1, b1, w2, b2, ln_g, ln_b, wk, wv, wq, wo, bo
// ---------------------------------------------------------------------------
extern "C" void kernel_launch(void* const* d_in, const int* in_sizes, int n_in,
                              void* d_out, int out_size) {
    const int*   x     = (const int*)d_in[0];
    const float* embed = (const float*)d_in[1];
    const float* w1    = (const float*)d_in[2];
    const float* b1    = (const float*)d_in[3];
    const float* w2    = (const float*)d_in[4];
    const float* b2    = (const float*)d_in[5];
    const float* ln_g  = (const float*)d_in[6];
    const float* ln_b  = (const float*)d_in[7];
    const float* wk    = (const float*)d_in[8];
    const float* wv    = (const float*)d_in[9];
    const float* wq    = (const float*)d_in[10];
    const float* wo    = (const float*)d_in[11];
    const float* bo    = (const float*)d_in[12];
    float*       out   = (float*)d_out;

    build_tables<<<V, H>>>(embed, w1, b1, w2, b2, ln_g, ln_b, wk, wv, wq);
    scan_kernel<<<B, 32>>>(x, wo, bo, out);
}

// round 10
// speedup vs baseline: 1.9802x; 1.9802x over previous
#include <cuda_runtime.h>
#include <cuda_bf16.h>
#include <cstdint>

// ---------------------------------------------------------------------------
// DeltaOnlyModel: B=256, L=2048, H=V=64.
// Encoder collapses to 64-entry vocab tables (k normalized, v, q, thr^2) plus
// the key Gram matrix. Scan: 1 block/batch, 64 threads, M row/thread in regs.
// PAIR CHUNKING: two tokens per iteration, one butterfly+exchange per pair,
// exact in-pair gate algebra via the Gram scalar, block-uniform skip of the
// (usually idle) rank-1 updates.
// ---------------------------------------------------------------------------

#define H 64
#define V 64
#define L 2048
#define B 256

__device__ float g_ktab[V * H];
__device__ float g_vtab[V * H];
__device__ float g_qtab[V * H];
__device__ float g_gram[V * V];
__device__ float g_thr2[V];

typedef unsigned long long ull;

__device__ __forceinline__ ull ffma2(ull a, ull b, ull c) {
    ull d;
    asm("fma.rn.f32x2 %0, %1, %2, %3;" : "=l"(d) : "l"(a), "l"(b), "l"(c));
    return d;
}
__device__ __forceinline__ ull fadd2(ull a, ull b) {
    ull d;
    asm("add.rn.f32x2 %0, %1, %2;" : "=l"(d) : "l"(a), "l"(b));
    return d;
}
__device__ __forceinline__ ull pack2(float lo, float hi) {
    ull d;
    asm("mov.b64 %0, {%1, %2};" : "=l"(d) : "f"(lo), "f"(hi));
    return d;
}
__device__ __forceinline__ void unpack2(ull a, float& lo, float& hi) {
    asm("mov.b64 {%0, %1}, %2;" : "=f"(lo), "=f"(hi) : "l"(a));
}
__device__ __forceinline__ float hsum4(ull a0, ull a1, ull a2, ull a3) {
    float lo, hi;
    unpack2(fadd2(fadd2(a0, a1), fadd2(a2, a3)), lo, hi);
    return lo + hi;
}

// ---------------------------------------------------------------------------
// Table builder: one block per vocab entry, 64 threads.
// ---------------------------------------------------------------------------
__global__ void build_tables(const float* __restrict__ embed,
                             const float* __restrict__ w1,
                             const float* __restrict__ b1,
                             const float* __restrict__ w2,
                             const float* __restrict__ b2,
                             const float* __restrict__ ln_g,
                             const float* __restrict__ ln_b,
                             const float* __restrict__ wk,
                             const float* __restrict__ wv,
                             const float* __restrict__ wq) {
    __shared__ float se[H];
    __shared__ float su[2 * H];
    __shared__ float sh[H];
    __shared__ float sred[H];

    const int c = blockIdx.x;
    const int j = threadIdx.x;

    se[j] = embed[c * H + j];
    __syncthreads();

    #pragma unroll
    for (int rep = 0; rep < 2; rep++) {
        const int m = j + rep * H;
        float a = b1[m];
        #pragma unroll 8
        for (int i = 0; i < H; i++) a = fmaf(se[i], w1[i * (2 * H) + m], a);
        su[m] = fmaxf(a, 0.0f);
    }
    __syncthreads();

    float f = b2[j];
    #pragma unroll 8
    for (int m = 0; m < 2 * H; m++) f = fmaf(su[m], w2[m * H + j], f);

    const float s = se[j] + f;
    sh[j] = s;
    __syncthreads();

    float mu = 0.0f;
    #pragma unroll 8
    for (int i = 0; i < H; i++) mu += sh[i];
    mu *= (1.0f / H);
    float var = 0.0f;
    #pragma unroll 8
    for (int i = 0; i < H; i++) { float d = sh[i] - mu; var = fmaf(d, d, var); }
    var *= (1.0f / H);
    const float hn = (s - mu) * rsqrtf(var + 1e-5f) * ln_g[j] + ln_b[j];
    __syncthreads();
    sh[j] = hn;
    __syncthreads();

    float kr = 0.0f;
    #pragma unroll 8
    for (int i = 0; i < H; i++) kr = fmaf(sh[i], wk[i * H + j], kr);
    sred[j] = kr * kr;
    __syncthreads();
    float nk = 0.0f;
    #pragma unroll 8
    for (int i = 0; i < H; i++) nk += sred[i];
    nk = fmaxf(sqrtf(nk), 1e-12f);
    g_ktab[c * H + j] = kr / nk;
    __syncthreads();

    float vr = 0.0f;
    #pragma unroll 8
    for (int i = 0; i < H; i++) vr = fmaf(sh[i], wv[i * H + j], vr);
    g_vtab[c * H + j] = vr;
    sred[j] = vr * vr;
    __syncthreads();
    float nv = 0.0f;
    #pragma unroll 8
    for (int i = 0; i < H; i++) nv += sred[i];
    if (j == 0) g_thr2[c] = 0.16f * nv;

    float qr = 0.0f;
    #pragma unroll 8
    for (int i = 0; i < H; i++) qr = fmaf(sh[i], wq[i * H + j], qr);
    g_qtab[c * H + j] = qr;
}

// Gram matrix of normalized keys: G[a][b] = k_a . k_b
__global__ void gram_kernel() {
    __shared__ float ka[H];
    const int a = blockIdx.x;
    const int j = threadIdx.x;
    ka[j] = g_ktab[a * H + j];
    __syncthreads();
    float s = 0.0f;
    #pragma unroll 8
    for (int i = 0; i < H; i++) s = fmaf(ka[i], g_ktab[j * H + i], s);
    g_gram[a * H + j] = s;
}

// ---------------------------------------------------------------------------
// Scan kernel: pair-chunked.
// ---------------------------------------------------------------------------
__global__ __launch_bounds__(64) void scan_kernel(const int* __restrict__ x,
                                                  const float* __restrict__ wo,
                                                  const float* __restrict__ bo,
                                                  float* __restrict__ out) {
    __shared__ __align__(16) float sk[V * H];   // 16 KB normalized k
    __shared__ float sv[V * H];                 // 16 KB v table
    __shared__ float sG[V * V];                 // 16 KB Gram
    __shared__ float sthr[V];
    __shared__ int   sx[L];                     // 8 KB tokens
    __shared__ ull   sxA[2][2];                 // [parity][warp] packed (S00,S01)
    __shared__ float sxB[2][2];                 // [parity][warp] S11
    __shared__ float sfin[H];

    const int b    = blockIdx.x;
    const int tid  = threadIdx.x;
    const int lane = tid & 31;
    const int w    = tid >> 5;

    for (int i = tid; i < V * H; i += 64) {
        sk[i] = g_ktab[i];
        sv[i] = g_vtab[i];
        sG[i] = g_gram[i];
    }
    sthr[tid] = g_thr2[tid];
    const int* xb = x + b * L;
    for (int i = tid; i < L; i += 64) sx[i] = xb[i];
    __syncthreads();

    ull m2[32];
    #pragma unroll
    for (int i = 0; i < 32; i++) m2[i] = 0ULL;

    for (int t = 0; t < L; t += 2) {
        const int tok0 = sx[t];
        const int tok1 = sx[t + 1];

        // early scalar/table fetches (off the FMA critical path)
        const float thr0 = sthr[tok0];
        const float thr1 = sthr[tok1];
        const float G01  = sG[(tok0 << 6) + tok1];
        const float v0   = sv[(tok0 << 6) + tid];
        const float v1   = sv[(tok1 << 6) + tid];

        // preds for both tokens vs block-entry M
        const ulonglong2* kp0 = reinterpret_cast<const ulonglong2*>(sk + (tok0 << 6));
        const ulonglong2* kp1 = reinterpret_cast<const ulonglong2*>(sk + (tok1 << 6));
        ull a0 = 0, a1 = 0, a2 = 0, a3 = 0;
        ull c0 = 0, c1 = 0, c2 = 0, c3 = 0;
        #pragma unroll
        for (int j = 0; j < 8; j++) {
            const ulonglong2 kA0 = kp0[2 * j];
            const ulonglong2 kB0 = kp0[2 * j + 1];
            const ulonglong2 kA1 = kp1[2 * j];
            const ulonglong2 kB1 = kp1[2 * j + 1];
            a0 = ffma2(m2[4 * j + 0], kA0.x, a0);
            a1 = ffma2(m2[4 * j + 1], kA0.y, a1);
            a2 = ffma2(m2[4 * j + 2], kB0.x, a2);
            a3 = ffma2(m2[4 * j + 3], kB0.y, a3);
            c0 = ffma2(m2[4 * j + 0], kA1.x, c0);
            c1 = ffma2(m2[4 * j + 1], kA1.y, c1);
            c2 = ffma2(m2[4 * j + 2], kB1.x, c2);
            c3 = ffma2(m2[4 * j + 3], kB1.y, c3);
        }
        const float P0 = hsum4(a0, a1, a2, a3);
        const float P1 = hsum4(c0, c1, c2, c3);

        const float r0 = v0 - P0;
        const float r1 = v1 - P1;

        // three global sums: (S00,S01) packed + S11, one butterfly phase
        ull  u = pack2(r0 * r0, r0 * r1);
        float s11 = r1 * r1;
        #pragma unroll
        for (int o = 16; o > 0; o >>= 1) {
            u   = fadd2(u, __shfl_xor_sync(0xffffffffu, u, o));
            s11 += __shfl_xor_sync(0xffffffffu, s11, o);
        }
        const int pb = (t >> 1) & 1;
        if (lane == 0) { sxA[pb][w] = u; sxB[pb][w] = s11; }
        __syncthreads();
        float S00, S01;
        unpack2(fadd2(sxA[pb][0], sxA[pb][1]), S00, S01);
        const float S11 = sxB[pb][0] + sxB[pb][1];

        // exact in-pair gate algebra
        const bool g0 = S00 > thr0;
        const float w10 = g0 ? -G01 : 0.0f;
        const float n1  = S11 + w10 * (2.0f * S01 + w10 * S00);
        const bool g1 = n1 > thr1;

        if (g0 | g1) {
            const float du0 = g0 ? r0 : 0.0f;
            const float du1 = g1 ? fmaf(w10, r0, r1) : 0.0f;
            const ull dd0 = pack2(du0, du0);
            const ull dd1 = pack2(du1, du1);
            #pragma unroll
            for (int j = 0; j < 8; j++) {
                const ulonglong2 kA0 = kp0[2 * j];
                const ulonglong2 kB0 = kp0[2 * j + 1];
                const ulonglong2 kA1 = kp1[2 * j];
                const ulonglong2 kB1 = kp1[2 * j + 1];
                m2[4 * j + 0] = ffma2(dd1, kA1.x, ffma2(dd0, kA0.x, m2[4 * j + 0]));
                m2[4 * j + 1] = ffma2(dd1, kA1.y, ffma2(dd0, kA0.y, m2[4 * j + 1]));
                m2[4 * j + 2] = ffma2(dd1, kB1.x, ffma2(dd0, kB0.x, m2[4 * j + 2]));
                m2[4 * j + 3] = ffma2(dd1, kB1.y, ffma2(dd0, kB0.y, m2[4 * j + 3]));
            }
        }
    }

    // Readout: q = q_tab[last token]; read = relu(M q); out = read @ wo + bo
    const int tokL = sx[L - 1];
    const float* qv = g_qtab + (tokL << 6);
    float r = 0.0f;
    #pragma unroll
    for (int j = 0; j < 32; j++) {
        float lo, hi;
        unpack2(m2[j], lo, hi);
        r = fmaf(lo, qv[2 * j], r);
        r = fmaf(hi, qv[2 * j + 1], r);
    }
    r = fmaxf(r, 0.0f);
    sfin[tid] = r;
    __syncthreads();

    float oacc = bo[tid];
    #pragma unroll 8
    for (int i = 0; i < H; i++) oacc = fmaf(sfin[i], wo[(i << 6) + tid], oacc);
    out[(b << 6) + tid] = oacc;
}

// ---------------------------------------------------------------------------
// Inputs: x, embed, w1, b1, w2, b2, ln_g, ln_b, wk, wv, wq, wo, bo
// ---------------------------------------------------------------------------
extern "C" void kernel_launch(void* const* d_in, const int* in_sizes, int n_in,
                              void* d_out, int out_size) {
    const int*   x     = (const int*)d_in[0];
    const float* embed = (const float*)d_in[1];
    const float* w1    = (const float*)d_in[2];
    const float* b1    = (const float*)d_in[3];
    const float* w2    = (const float*)d_in[4];
    const float* b2    = (const float*)d_in[5];
    const float* ln_g  = (const float*)d_in[6];
    const float* ln_b  = (const float*)d_in[7];
    const float* wk    = (const float*)d_in[8];
    const float* wv    = (const float*)d_in[9];
    const float* wq    = (const float*)d_in[10];
    const float* wo    = (const float*)d_in[11];
    const float* bo    = (const float*)d_in[12];
    float*       out   = (float*)d_out;

    build_tables<<<V, H>>>(embed, w1, b1, w2, b2, ln_g, ln_b, wk, wv, wq);
    gram_kernel<<<V, H>>>();
    scan_kernel<<<B, H>>>(x, wo, bo, out);
}

// round 11
// speedup vs baseline: 2.3383x; 1.1808x over previous
#include <cuda_runtime.h>
#include <cuda_bf16.h>
#include <cstdint>

// ---------------------------------------------------------------------------
// DeltaOnlyModel: B=256, L=2048, H=V=64.
// Encoder collapses to 64-entry vocab tables (k normalized, v, q, thr^2) plus
// the key Gram matrix. Scan: 1 block/batch, 64 threads, M row/thread in regs.
// QUAD CHUNKING: four tokens per iteration, ONE butterfly+exchange per quad,
// exact in-quad gate algebra via Gram scalars (validated in R3), and a
// block-uniform skip of the combined rank-1 updates.
// ---------------------------------------------------------------------------

#define H 64
#define V 64
#define L 2048
#define B 256

__device__ float g_ktab[V * H];
__device__ float g_vtab[V * H];
__device__ float g_qtab[V * H];
__device__ float g_gram[V * V];
__device__ float g_thr2[V];

typedef unsigned long long ull;

__device__ __forceinline__ ull ffma2(ull a, ull b, ull c) {
    ull d;
    asm("fma.rn.f32x2 %0, %1, %2, %3;" : "=l"(d) : "l"(a), "l"(b), "l"(c));
    return d;
}
__device__ __forceinline__ ull fadd2(ull a, ull b) {
    ull d;
    asm("add.rn.f32x2 %0, %1, %2;" : "=l"(d) : "l"(a), "l"(b));
    return d;
}
__device__ __forceinline__ ull pack2(float lo, float hi) {
    ull d;
    asm("mov.b64 %0, {%1, %2};" : "=l"(d) : "f"(lo), "f"(hi));
    return d;
}
__device__ __forceinline__ void unpack2(ull a, float& lo, float& hi) {
    asm("mov.b64 {%0, %1}, %2;" : "=f"(lo), "=f"(hi) : "l"(a));
}
__device__ __forceinline__ float hsum4(ull a0, ull a1, ull a2, ull a3) {
    float lo, hi;
    unpack2(fadd2(fadd2(a0, a1), fadd2(a2, a3)), lo, hi);
    return lo + hi;
}

// ---------------------------------------------------------------------------
// Table builder: one block per vocab entry, 64 threads.
// ---------------------------------------------------------------------------
__global__ void build_tables(const float* __restrict__ embed,
                             const float* __restrict__ w1,
                             const float* __restrict__ b1,
                             const float* __restrict__ w2,
                             const float* __restrict__ b2,
                             const float* __restrict__ ln_g,
                             const float* __restrict__ ln_b,
                             const float* __restrict__ wk,
                             const float* __restrict__ wv,
                             const float* __restrict__ wq) {
    __shared__ float se[H];
    __shared__ float su[2 * H];
    __shared__ float sh[H];
    __shared__ float sred[H];

    const int c = blockIdx.x;
    const int j = threadIdx.x;

    se[j] = embed[c * H + j];
    __syncthreads();

    #pragma unroll
    for (int rep = 0; rep < 2; rep++) {
        const int m = j + rep * H;
        float a = b1[m];
        #pragma unroll 8
        for (int i = 0; i < H; i++) a = fmaf(se[i], w1[i * (2 * H) + m], a);
        su[m] = fmaxf(a, 0.0f);
    }
    __syncthreads();

    float f = b2[j];
    #pragma unroll 8
    for (int m = 0; m < 2 * H; m++) f = fmaf(su[m], w2[m * H + j], f);

    const float s = se[j] + f;
    sh[j] = s;
    __syncthreads();

    float mu = 0.0f;
    #pragma unroll 8
    for (int i = 0; i < H; i++) mu += sh[i];
    mu *= (1.0f / H);
    float var = 0.0f;
    #pragma unroll 8
    for (int i = 0; i < H; i++) { float d = sh[i] - mu; var = fmaf(d, d, var); }
    var *= (1.0f / H);
    const float hn = (s - mu) * rsqrtf(var + 1e-5f) * ln_g[j] + ln_b[j];
    __syncthreads();
    sh[j] = hn;
    __syncthreads();

    float kr = 0.0f;
    #pragma unroll 8
    for (int i = 0; i < H; i++) kr = fmaf(sh[i], wk[i * H + j], kr);
    sred[j] = kr * kr;
    __syncthreads();
    float nk = 0.0f;
    #pragma unroll 8
    for (int i = 0; i < H; i++) nk += sred[i];
    nk = fmaxf(sqrtf(nk), 1e-12f);
    g_ktab[c * H + j] = kr / nk;
    __syncthreads();

    float vr = 0.0f;
    #pragma unroll 8
    for (int i = 0; i < H; i++) vr = fmaf(sh[i], wv[i * H + j], vr);
    g_vtab[c * H + j] = vr;
    sred[j] = vr * vr;
    __syncthreads();
    float nv = 0.0f;
    #pragma unroll 8
    for (int i = 0; i < H; i++) nv += sred[i];
    if (j == 0) g_thr2[c] = 0.16f * nv;

    float qr = 0.0f;
    #pragma unroll 8
    for (int i = 0; i < H; i++) qr = fmaf(sh[i], wq[i * H + j], qr);
    g_qtab[c * H + j] = qr;
}

// Gram matrix of normalized keys: G[a][b] = k_a . k_b
__global__ void gram_kernel() {
    __shared__ float ka[H];
    const int a = blockIdx.x;
    const int j = threadIdx.x;
    ka[j] = g_ktab[a * H + j];
    __syncthreads();
    float s = 0.0f;
    #pragma unroll 8
    for (int i = 0; i < H; i++) s = fmaf(ka[i], g_ktab[j * H + i], s);
    g_gram[a * H + j] = s;
}

// ---------------------------------------------------------------------------
// Scan kernel: quad-chunked.
// ---------------------------------------------------------------------------
__global__ __launch_bounds__(64) void scan_kernel(const int* __restrict__ x,
                                                  const float* __restrict__ wo,
                                                  const float* __restrict__ bo,
                                                  float* __restrict__ out) {
    __shared__ __align__(16) float sk[V * H];   // 16 KB normalized k
    __shared__ float sv[V * H];                 // 16 KB v table
    __shared__ float sG[V * V];                 // 16 KB Gram
    __shared__ float sthr[V];
    __shared__ int   sx[L];                     // 8 KB tokens
    __shared__ ull   sxA[2][2][5];              // [parity][warp][5 packed sums]
    __shared__ float sfin[H];

    const int b    = blockIdx.x;
    const int tid  = threadIdx.x;
    const int lane = tid & 31;
    const int w    = tid >> 5;

    for (int i = tid; i < V * H; i += 64) {
        sk[i] = g_ktab[i];
        sv[i] = g_vtab[i];
        sG[i] = g_gram[i];
    }
    sthr[tid] = g_thr2[tid];
    const int* xb = x + b * L;
    for (int i = tid; i < L; i += 64) sx[i] = xb[i];
    __syncthreads();

    ull m2[32];
    #pragma unroll
    for (int i = 0; i < 32; i++) m2[i] = 0ULL;

    for (int t = 0; t < L; t += 4) {
        const int tok0 = sx[t];
        const int tok1 = sx[t + 1];
        const int tok2 = sx[t + 2];
        const int tok3 = sx[t + 3];

        // early scalar/table fetches (off the FMA critical path)
        const float thr0 = sthr[tok0], thr1 = sthr[tok1];
        const float thr2 = sthr[tok2], thr3 = sthr[tok3];
        const float G01 = sG[(tok0 << 6) + tok1];
        const float G02 = sG[(tok0 << 6) + tok2];
        const float G03 = sG[(tok0 << 6) + tok3];
        const float G12 = sG[(tok1 << 6) + tok2];
        const float G13 = sG[(tok1 << 6) + tok3];
        const float G23 = sG[(tok2 << 6) + tok3];
        const float v0 = sv[(tok0 << 6) + tid];
        const float v1 = sv[(tok1 << 6) + tid];
        const float v2 = sv[(tok2 << 6) + tid];
        const float v3 = sv[(tok3 << 6) + tid];

        const ulonglong2* kp0 = reinterpret_cast<const ulonglong2*>(sk + (tok0 << 6));
        const ulonglong2* kp1 = reinterpret_cast<const ulonglong2*>(sk + (tok1 << 6));
        const ulonglong2* kp2 = reinterpret_cast<const ulonglong2*>(sk + (tok2 << 6));
        const ulonglong2* kp3 = reinterpret_cast<const ulonglong2*>(sk + (tok3 << 6));

        // preds for all four tokens vs block-entry M (16 packed accumulators)
        ull a0 = 0, a1 = 0, a2 = 0, a3 = 0;
        ull c0 = 0, c1 = 0, c2 = 0, c3 = 0;
        ull e0 = 0, e1 = 0, e2 = 0, e3 = 0;
        ull f0 = 0, f1 = 0, f2 = 0, f3 = 0;
        #pragma unroll
        for (int j = 0; j < 8; j++) {
            const ulonglong2 kA0 = kp0[2 * j], kB0 = kp0[2 * j + 1];
            const ulonglong2 kA1 = kp1[2 * j], kB1 = kp1[2 * j + 1];
            const ulonglong2 kA2 = kp2[2 * j], kB2 = kp2[2 * j + 1];
            const ulonglong2 kA3 = kp3[2 * j], kB3 = kp3[2 * j + 1];
            const ull m0 = m2[4 * j + 0], m1 = m2[4 * j + 1];
            const ull m2_ = m2[4 * j + 2], m3 = m2[4 * j + 3];
            a0 = ffma2(m0, kA0.x, a0); a1 = ffma2(m1, kA0.y, a1);
            a2 = ffma2(m2_, kB0.x, a2); a3 = ffma2(m3, kB0.y, a3);
            c0 = ffma2(m0, kA1.x, c0); c1 = ffma2(m1, kA1.y, c1);
            c2 = ffma2(m2_, kB1.x, c2); c3 = ffma2(m3, kB1.y, c3);
            e0 = ffma2(m0, kA2.x, e0); e1 = ffma2(m1, kA2.y, e1);
            e2 = ffma2(m2_, kB2.x, e2); e3 = ffma2(m3, kB2.y, e3);
            f0 = ffma2(m0, kA3.x, f0); f1 = ffma2(m1, kA3.y, f1);
            f2 = ffma2(m2_, kB3.x, f2); f3 = ffma2(m3, kB3.y, f3);
        }
        const float r0 = v0 - hsum4(a0, a1, a2, a3);
        const float r1 = v1 - hsum4(c0, c1, c2, c3);
        const float r2 = v2 - hsum4(e0, e1, e2, e3);
        const float r3 = v3 - hsum4(f0, f1, f2, f3);

        // 10 dot products packed as 5 f32x2, single butterfly phase
        ull u0 = pack2(r0 * r0, r0 * r1);
        ull u1 = pack2(r0 * r2, r0 * r3);
        ull u2 = pack2(r1 * r1, r1 * r2);
        ull u3 = pack2(r1 * r3, r2 * r2);
        ull u4 = pack2(r2 * r3, r3 * r3);
        #pragma unroll
        for (int o = 16; o > 0; o >>= 1) {
            u0 = fadd2(u0, __shfl_xor_sync(0xffffffffu, u0, o));
            u1 = fadd2(u1, __shfl_xor_sync(0xffffffffu, u1, o));
            u2 = fadd2(u2, __shfl_xor_sync(0xffffffffu, u2, o));
            u3 = fadd2(u3, __shfl_xor_sync(0xffffffffu, u3, o));
            u4 = fadd2(u4, __shfl_xor_sync(0xffffffffu, u4, o));
        }
        const int pb = (t >> 2) & 1;
        if (lane == 0) {
            sxA[pb][w][0] = u0; sxA[pb][w][1] = u1; sxA[pb][w][2] = u2;
            sxA[pb][w][3] = u3; sxA[pb][w][4] = u4;
        }
        __syncthreads();
        float S00, S01, S02, S03, S11, S12, S13, S22, S23, S33;
        unpack2(fadd2(sxA[pb][0][0], sxA[pb][1][0]), S00, S01);
        unpack2(fadd2(sxA[pb][0][1], sxA[pb][1][1]), S02, S03);
        unpack2(fadd2(sxA[pb][0][2], sxA[pb][1][2]), S11, S12);
        unpack2(fadd2(sxA[pb][0][3], sxA[pb][1][3]), S13, S22);
        unpack2(fadd2(sxA[pb][0][4], sxA[pb][1][4]), S23, S33);

        // exact in-quad gate algebra (validated numerically in R3)
        const bool g0 = S00 > thr0;
        const float w10 = g0 ? -G01 : 0.0f;
        const float n1s = S11 + w10 * (2.0f * S01 + w10 * S00);
        const bool g1 = n1s > thr1;
        const float w21 = g1 ? -G12 : 0.0f;
        const float w20 = (g0 ? -G02 : 0.0f) + w21 * w10;
        const float n2s = S22 + w20 * (w20 * S00 + 2.0f * S02)
                              + w21 * (w21 * S11 + 2.0f * S12)
                              + 2.0f * w20 * w21 * S01;
        const bool g2 = n2s > thr2;
        const float w32 = g2 ? -G23 : 0.0f;
        const float t13 = g1 ? -G13 : 0.0f;
        const float w31 = t13 + w32 * w21;
        const float w30 = (g0 ? -G03 : 0.0f) + t13 * w10 + w32 * w20;
        const float n3s = S33 + w30 * (w30 * S00 + 2.0f * S03)
                              + w31 * (w31 * S11 + 2.0f * S13)
                              + w32 * (w32 * S22 + 2.0f * S23)
                              + 2.0f * (w30 * w31 * S01 + w30 * w32 * S02 + w31 * w32 * S12);
        const bool g3 = n3s > thr3;

        if (g0 | g1 | g2 | g3) {
            const float du0 = g0 ? r0 : 0.0f;
            const float du1 = g1 ? (r1 + w10 * r0) : 0.0f;
            const float du2 = g2 ? (r2 + w20 * r0 + w21 * r1) : 0.0f;
            const float du3 = g3 ? (r3 + w30 * r0 + w31 * r1 + w32 * r2) : 0.0f;
            const ull dd0 = pack2(du0, du0);
            const ull dd1 = pack2(du1, du1);
            const ull dd2 = pack2(du2, du2);
            const ull dd3 = pack2(du3, du3);
            #pragma unroll
            for (int j = 0; j < 8; j++) {
                const ulonglong2 kA0 = kp0[2 * j], kB0 = kp0[2 * j + 1];
                const ulonglong2 kA1 = kp1[2 * j], kB1 = kp1[2 * j + 1];
                const ulonglong2 kA2 = kp2[2 * j], kB2 = kp2[2 * j + 1];
                const ulonglong2 kA3 = kp3[2 * j], kB3 = kp3[2 * j + 1];
                m2[4 * j + 0] = ffma2(dd3, kA3.x, ffma2(dd2, kA2.x,
                                 ffma2(dd1, kA1.x, ffma2(dd0, kA0.x, m2[4 * j + 0]))));
                m2[4 * j + 1] = ffma2(dd3, kA3.y, ffma2(dd2, kA2.y,
                                 ffma2(dd1, kA1.y, ffma2(dd0, kA0.y, m2[4 * j + 1]))));
                m2[4 * j + 2] = ffma2(dd3, kB3.x, ffma2(dd2, kB2.x,
                                 ffma2(dd1, kB1.x, ffma2(dd0, kB0.x, m2[4 * j + 2]))));
                m2[4 * j + 3] = ffma2(dd3, kB3.y, ffma2(dd2, kB2.y,
                                 ffma2(dd1, kB1.y, ffma2(dd0, kB0.y, m2[4 * j + 3]))));
            }
        }
    }

    // Readout: q = q_tab[last token]; read = relu(M q); out = read @ wo + bo
    const int tokL = sx[L - 1];
    const float* qv = g_qtab + (tokL << 6);
    float r = 0.0f;
    #pragma unroll
    for (int j = 0; j < 32; j++) {
        float lo, hi;
        unpack2(m2[j], lo, hi);
        r = fmaf(lo, qv[2 * j], r);
        r = fmaf(hi, qv[2 * j + 1], r);
    }
    r = fmaxf(r, 0.0f);
    sfin[tid] = r;
    __syncthreads();

    float oacc = bo[tid];
    #pragma unroll 8
    for (int i = 0; i < H; i++) oacc = fmaf(sfin[i], wo[(i << 6) + tid], oacc);
    out[(b << 6) + tid] = oacc;
}

// ---------------------------------------------------------------------------
// Inputs: x, embed, w1, b1, w2, b2, ln_g, ln_b, wk, wv, wq, wo, bo
// ---------------------------------------------------------------------------
extern "C" void kernel_launch(void* const* d_in, const int* in_sizes, int n_in,
                              void* d_out, int out_size) {
    const int*   x     = (const int*)d_in[0];
    const float* embed = (const float*)d_in[1];
    const float* w1    = (const float*)d_in[2];
    const float* b1    = (const float*)d_in[3];
    const float* w2    = (const float*)d_in[4];
    const float* b2    = (const float*)d_in[5];
    const float* ln_g  = (const float*)d_in[6];
    const float* ln_b  = (const float*)d_in[7];
    const float* wk    = (const float*)d_in[8];
    const float* wv    = (const float*)d_in[9];
    const float* wq    = (const float*)d_in[10];
    const float* wo    = (const float*)d_in[11];
    const float* bo    = (const float*)d_in[12];
    float*       out   = (float*)d_out;

    build_tables<<<V, H>>>(embed, w1, b1, w2, b2, ln_g, ln_b, wk, wv, wq);
    gram_kernel<<<V, H>>>();
    scan_kernel<<<B, H>>>(x, wo, bo, out);
}